// round 2
// baseline (speedup 1.0000x reference)
#include <cuda_runtime.h>

#define B   128
#define M   200
#define S   20
#define D   128
#define NC  10000
#define CL  10
#define HOPS 3

// Scratch (no cudaMalloc allowed)
__device__ float g_m[B * M * D];      // 13.1 MB: memory encodings
__device__ float g_u[B * D];          // query state
__device__ float g_cand[NC * D];      // candidate sums

// ---------------------------------------------------------------------------
// Kernel 1: m[b,mm,:] = sum_s A[stories[b,mm,s]]   (pad idx 0 -> zero row)
//           u[b,:]    = sum_s A[queries[b,s]]
// One block per (b,mm) row; thread t owns column t. Loads of A rows are
// perfectly coalesced 512B transactions; massive grid gives MLP for the
// random-gather latency. NOTE: harness delivers int64 tensors as int32.
// ---------------------------------------------------------------------------
__global__ void gather_mu_kernel(const int* __restrict__ stories,
                                 const int* __restrict__ queries,
                                 const float* __restrict__ A) {
    __shared__ int sidx[S];
    const int bi = blockIdx.x;
    const int t  = threadIdx.x;

    if (bi < B * M) {
        if (t < S) sidx[t] = stories[(size_t)bi * S + t];
        __syncthreads();
        float acc = 0.f;
#pragma unroll
        for (int s = 0; s < S; s++) {
            int idx = sidx[s];
            if (idx != 0) acc += A[(size_t)idx * D + t];
        }
        g_m[(size_t)bi * D + t] = acc;
    } else {
        const int b = bi - B * M;
        if (t < S) sidx[t] = queries[b * S + t];
        __syncthreads();
        float acc = 0.f;
#pragma unroll
        for (int s = 0; s < S; s++) {
            int idx = sidx[s];
            if (idx != 0) acc += A[(size_t)idx * D + t];
        }
        g_u[b * D + t] = acc;
    }
}

// ---------------------------------------------------------------------------
// Kernel 2: cand_sum[c,:] = sum_l W[candidates[c,l]]
// ---------------------------------------------------------------------------
__global__ void gather_cand_kernel(const int* __restrict__ cand,
                                   const float* __restrict__ W) {
    __shared__ int sidx[CL];
    const int c = blockIdx.x;
    const int t = threadIdx.x;
    if (t < CL) sidx[t] = cand[(size_t)c * CL + t];
    __syncthreads();
    float acc = 0.f;
#pragma unroll
    for (int l = 0; l < CL; l++) {
        int idx = sidx[l];
        if (idx != 0) acc += W[(size_t)idx * D + t];
    }
    g_cand[c * D + t] = acc;
}

// ---------------------------------------------------------------------------
// Kernel 3: 3 attention hops, one block per batch element.
// m[b] (100KB) + H_w (pitch 129, 64.5KB) staged in smem once, reused 3 hops.
// ---------------------------------------------------------------------------
#define HW_PITCH 129
#define HOP_THREADS 256

__global__ void hops_kernel(const float* __restrict__ Hw) {
    extern __shared__ float smem[];
    float* sm_m   = smem;                        // M*D
    float* sm_h   = sm_m + M * D;                // D*HW_PITCH
    float* sm_u   = sm_h + D * HW_PITCH;         // D
    float* sm_dot = sm_u + D;                    // M
    float* sm_red = sm_dot + M;                  // HOP_THREADS

    const int b  = blockIdx.x;
    const int t  = threadIdx.x;

    // stage m tile (float4) and H_w (padded rows: kills 32-way conflicts)
    {
        const float4* gm4 = (const float4*)(g_m + (size_t)b * M * D);
        float4* sm4 = (float4*)sm_m;
        for (int i = t; i < M * D / 4; i += HOP_THREADS) sm4[i] = gm4[i];
        for (int i = t; i < D * D; i += HOP_THREADS) {
            int d = i >> 7, k = i & 127;
            sm_h[d * HW_PITCH + k] = Hw[i];
        }
        if (t < D) sm_u[t] = g_u[b * D + t];
    }
    __syncthreads();

    const int warp = t >> 5, lane = t & 31;

    for (int hop = 0; hop < HOPS; hop++) {
        // dotted[mm] = <m[mm], u>  -- one warp per row, 25 rows/warp
        for (int mm = warp; mm < M; mm += HOP_THREADS / 32) {
            const float* row = sm_m + mm * D;
            float s = 0.f;
#pragma unroll
            for (int k = lane; k < D; k += 32) s += row[k] * sm_u[k];
#pragma unroll
            for (int off = 16; off; off >>= 1)
                s += __shfl_xor_sync(0xffffffffu, s, off);
            if (lane == 0) sm_dot[mm] = s;
        }
        __syncthreads();

        // softmax over M
        float lm = -1e30f;
        for (int i = t; i < M; i += HOP_THREADS) lm = fmaxf(lm, sm_dot[i]);
        sm_red[t] = lm; __syncthreads();
        for (int s = HOP_THREADS / 2; s > 0; s >>= 1) {
            if (t < s) sm_red[t] = fmaxf(sm_red[t], sm_red[t + s]);
            __syncthreads();
        }
        const float mx = sm_red[0];
        __syncthreads();

        float ls = 0.f;
        for (int i = t; i < M; i += HOP_THREADS) {
            float e = __expf(sm_dot[i] - mx);
            sm_dot[i] = e;
            ls += e;
        }
        sm_red[t] = ls; __syncthreads();
        for (int s = HOP_THREADS / 2; s > 0; s >>= 1) {
            if (t < s) sm_red[t] += sm_red[t + s];
            __syncthreads();
        }
        const float inv = 1.f / sm_red[0];
        __syncthreads();

        // o[d] = inv * sum_mm e[mm]*m[mm][d];  u = tanh(Hw @ u + o)
        float unew = 0.f;
        if (t < D) {
            float o = 0.f;
            for (int mm = 0; mm < M; mm++)
                o += sm_dot[mm] * sm_m[mm * D + t];
            o *= inv;
            float h = 0.f;
            const float* hr = sm_h + t * HW_PITCH;
#pragma unroll 8
            for (int k = 0; k < D; k++) h += hr[k] * sm_u[k];
            unew = tanhf(h + o);
        }
        __syncthreads();
        if (t < D) sm_u[t] = unew;
        __syncthreads();
    }
    if (t < D) g_u[b * D + t] = sm_u[t];
}

// ---------------------------------------------------------------------------
// Kernel 4: logits[b,c] = <u[b], cand_sum[c]>.  128x10000, K=128.
// Block computes a 128b x 128c tile; operands staged K-major in smem
// (pitch 132 -> float4-aligned, no severe conflicts); 8x8 register tiles.
// ---------------------------------------------------------------------------
#define GP 132   // smem pitch (floats), multiple of 4, not mult of 32

__global__ void gemm_kernel(float* __restrict__ out) {
    extern __shared__ float sm[];
    float* su = sm;            // su[k*GP + b]
    float* sc = sm + D * GP;   // sc[k*GP + c]
    const int t = threadIdx.x;
    const int cbase = blockIdx.x * 128;

    for (int i = t; i < B * D; i += 256) {
        int b = i >> 7, k = i & 127;
        su[k * GP + b] = g_u[i];
    }
    for (int i = t; i < 128 * D; i += 256) {
        int c = i >> 7, k = i & 127;
        int gc = cbase + c;
        sc[k * GP + c] = (gc < NC) ? g_cand[(size_t)gc * D + k] : 0.f;
    }
    __syncthreads();

    const int tx = t & 15, ty = t >> 4;
    const int b0 = ty * 8, c0 = tx * 8;
    float acc[8][8] = {};

#pragma unroll 4
    for (int k = 0; k < D; k++) {
        float4 a0 = *(const float4*)&su[k * GP + b0];
        float4 a1 = *(const float4*)&su[k * GP + b0 + 4];
        float4 v0 = *(const float4*)&sc[k * GP + c0];
        float4 v1 = *(const float4*)&sc[k * GP + c0 + 4];
        float av[8] = {a0.x, a0.y, a0.z, a0.w, a1.x, a1.y, a1.z, a1.w};
        float vv[8] = {v0.x, v0.y, v0.z, v0.w, v1.x, v1.y, v1.z, v1.w};
#pragma unroll
        for (int i = 0; i < 8; i++)
#pragma unroll
            for (int j = 0; j < 8; j++) acc[i][j] += av[i] * vv[j];
    }

#pragma unroll
    for (int i = 0; i < 8; i++) {
        const int b = b0 + i;
#pragma unroll
        for (int j = 0; j < 8; j += 4) {
            int gc = cbase + c0 + j;
            if (gc + 3 < NC) {
                *(float4*)&out[(size_t)b * NC + gc] =
                    make_float4(acc[i][j], acc[i][j + 1], acc[i][j + 2], acc[i][j + 3]);
            } else {
                for (int q = 0; q < 4; q++)
                    if (gc + q < NC) out[(size_t)b * NC + gc + q] = acc[i][j + q];
            }
        }
    }
}

// ---------------------------------------------------------------------------
extern "C" void kernel_launch(void* const* d_in, const int* in_sizes, int n_in,
                              void* d_out, int out_size) {
    const int*   stories    = (const int*)d_in[0];
    const int*   queries    = (const int*)d_in[1];
    const int*   candidates = (const int*)d_in[2];
    const float* A_tab      = (const float*)d_in[3];
    const float* W_tab      = (const float*)d_in[4];
    const float* H_w        = (const float*)d_in[5];
    float*       out        = (float*)d_out;

    const int hops_smem = (M * D + D * HW_PITCH + D + M + HOP_THREADS) * sizeof(float);
    const int gemm_smem = 2 * D * GP * sizeof(float);
    cudaFuncSetAttribute(hops_kernel, cudaFuncAttributeMaxDynamicSharedMemorySize, hops_smem);
    cudaFuncSetAttribute(gemm_kernel, cudaFuncAttributeMaxDynamicSharedMemorySize, gemm_smem);

    gather_mu_kernel<<<B * M + B, 128>>>(stories, queries, A_tab);
    gather_cand_kernel<<<NC, 128>>>(candidates, W_tab);
    hops_kernel<<<B, HOP_THREADS, hops_smem>>>(H_w);
    gemm_kernel<<<(NC + 127) / 128, 256, gemm_smem>>>(out);
}